// round 7
// baseline (speedup 1.0000x reference)
#include <cuda_runtime.h>
#include <cuda_bf16.h>
#include <math.h>

#define NN 50000
#define FIN 128
#define F1 256
#define HH 8
#define CH 32
#define NC 40
#define EMAX 1000000

// ---------------- scratch (device globals; no allocation allowed) -----------
__device__ __nv_bfloat16 g_h1bf[NN * F1];  // layer1 features, bf16, lane-permuted layout
__device__ float g_h2[NN * F1];            // elu(aggregated + b1)
__device__ float g_as1[NN * HH];
__device__ float g_ad1[NN * HH];
__device__ float g_g[NN * NC];             // layer2 per-node features
__device__ float g_a2s[NN];
__device__ float g_a2d[NN];
__device__ int   g_deg[NN];
__device__ int   g_rowptr[NN + 1];
__device__ int   g_cursor[NN + 1];
__device__ int   g_csrsrc[EMAX];
__device__ int   g_part[64];
__device__ int   g_is64;

// ---------------- helpers ---------------------------------------------------
__device__ __forceinline__ int edge_at(const void* p, long long i, int is64) {
    if (is64) return (int)((const long long*)p)[i];
    return ((const int*)p)[i];
}
__device__ __forceinline__ float lrelu(float v) { return v > 0.f ? v : 0.2f * v; }
__device__ __forceinline__ float eluf(float v) { return v > 0.f ? v : (__expf(v) - 1.f); }

__device__ __forceinline__ unsigned long long pkdup(float a) {
    unsigned long long r;
    asm("mov.b64 %0, {%1, %1};" : "=l"(r) : "f"(a));
    return r;
}
__device__ __forceinline__ unsigned long long pk2(float lo, float hi) {
    unsigned long long r;
    asm("mov.b64 %0, {%1, %2};" : "=l"(r) : "f"(lo), "f"(hi));
    return r;
}
__device__ __forceinline__ float2 unpk(unsigned long long v) {
    float2 r;
    asm("mov.b64 {%0, %1}, %2;" : "=f"(r.x), "=f"(r.y) : "l"(v));
    return r;
}
__device__ __forceinline__ void ffma2(unsigned long long& acc, unsigned long long a, unsigned long long b) {
    asm("fma.rn.f32x2 %0, %1, %2, %0;" : "+l"(acc) : "l"(a), "l"(b));
}

// ---------------- dtype detection ------------------------------------------
__global__ void k_detect(const void* ei, int n) {
    int bad = 0;
    for (int i = threadIdx.x; i < 1024; i += blockDim.x) {
        long long v = ((const long long*)ei)[i];
        if (v < 0 || v >= n) bad = 1;
    }
    int anybad = __syncthreads_or(bad);
    if (threadIdx.x == 0) g_is64 = anybad ? 0 : 1;
}

// ---------------- GEMM1 fused: h1 = x@W1, att scores, bf16 permuted output --
// BM=64, BN=256 (full width), BK=16, 256 threads, 8x8 per thread, f32x2 FMA.
__global__ void k_gemm1f(const float* __restrict__ x, const float* __restrict__ W1,
                         const float* __restrict__ a1s_, const float* __restrict__ a1d_, int n) {
    const int BM = 64, BK = 16;
    __shared__ float As[BK][BM];
    __shared__ float Bs[BK][F1];
    __shared__ float sas[BM][HH];
    __shared__ float sad[BM][HH];
    int t = threadIdx.x;
    int tx = t & 31;        // col group: cols tx*8..tx*8+7
    int ty = t >> 5;        // row group: rows ty*8..ty*8+7
    int bm0 = blockIdx.x * BM;

    for (int i = t; i < BM * HH; i += 256) {
        ((float*)sas)[i] = 0.f;
        ((float*)sad)[i] = 0.f;
    }

    unsigned long long acc2[8][4];
#pragma unroll
    for (int i = 0; i < 8; i++)
#pragma unroll
        for (int p = 0; p < 4; p++) acc2[i][p] = 0ull;

    int arow = t >> 2, akc = (t & 3) * 4;

    for (int kk = 0; kk < FIN; kk += BK) {
        float4 av = make_float4(0.f, 0.f, 0.f, 0.f);
        if (bm0 + arow < n)
            av = *(const float4*)&x[(long long)(bm0 + arow) * FIN + kk + akc];
        As[akc + 0][arow] = av.x;
        As[akc + 1][arow] = av.y;
        As[akc + 2][arow] = av.z;
        As[akc + 3][arow] = av.w;
#pragma unroll
        for (int j = 0; j < 4; j++) {
            int f4 = t + 256 * j;
            int brow = f4 >> 6, bcol = (f4 & 63) * 4;
            *(float4*)&Bs[brow][bcol] = *(const float4*)&W1[(long long)(kk + brow) * F1 + bcol];
        }
        __syncthreads();
#pragma unroll
        for (int k = 0; k < BK; k++) {
            float a[8];
            *(float4*)&a[0] = *(float4*)&As[k][ty * 8];
            *(float4*)&a[4] = *(float4*)&As[k][ty * 8 + 4];
            float4 bv0 = *(float4*)&Bs[k][tx * 8];
            float4 bv1 = *(float4*)&Bs[k][tx * 8 + 4];
            unsigned long long b2[4];
            b2[0] = pk2(bv0.x, bv0.y);
            b2[1] = pk2(bv0.z, bv0.w);
            b2[2] = pk2(bv1.x, bv1.y);
            b2[3] = pk2(bv1.z, bv1.w);
#pragma unroll
            for (int i = 0; i < 8; i++) {
                unsigned long long ad = pkdup(a[i]);
#pragma unroll
                for (int p = 0; p < 4; p++) ffma2(acc2[i][p], ad, b2[p]);
            }
        }
        __syncthreads();
    }

    // unpack accumulators
    float acc[8][8];
#pragma unroll
    for (int i = 0; i < 8; i++)
#pragma unroll
        for (int p = 0; p < 4; p++) {
            float2 v = unpk(acc2[i][p]);
            acc[i][2 * p] = v.x;
            acc[i][2 * p + 1] = v.y;
        }

    float cs[8], cd[8];
#pragma unroll
    for (int j = 0; j < 8; j++) {
        cs[j] = a1s_[tx * 8 + j];
        cd[j] = a1d_[tx * 8 + j];
    }
    int hh = tx >> 2;

    int base_e = (tx < 16) ? tx * 16 : (tx - 16) * 16 + 4;
#pragma unroll
    for (int i = 0; i < 8; i++) {
        int r = ty * 8 + i;
        int row = bm0 + r;
        float ps = 0.f, pd = 0.f;
#pragma unroll
        for (int j = 0; j < 8; j++) {
            ps += acc[i][j] * cs[j];
            pd += acc[i][j] * cd[j];
        }
        atomicAdd(&sas[r][hh], ps);
        atomicAdd(&sad[r][hh], pd);
        if (row < n) {
            __nv_bfloat162 p01 = __floats2bfloat162_rn(acc[i][0], acc[i][1]);
            __nv_bfloat162 p23 = __floats2bfloat162_rn(acc[i][2], acc[i][3]);
            __nv_bfloat162 p45 = __floats2bfloat162_rn(acc[i][4], acc[i][5]);
            __nv_bfloat162 p67 = __floats2bfloat162_rn(acc[i][6], acc[i][7]);
            __nv_bfloat162* dst = (__nv_bfloat162*)&g_h1bf[(long long)row * F1 + base_e];
            dst[0] = p01;
            dst[1] = p23;
            __nv_bfloat162* dst2 = (__nv_bfloat162*)&g_h1bf[(long long)row * F1 + base_e + 8];
            dst2[0] = p45;
            dst2[1] = p67;
        }
    }
    __syncthreads();
    for (int idx = t; idx < BM * HH; idx += 256) {
        int r = idx >> 3, h = idx & 7;
        if (bm0 + r < n) {
            g_as1[(bm0 + r) * HH + h] = sas[r][h];
            g_ad1[(bm0 + r) * HH + h] = sad[r][h];
        }
    }
}

// ---------------- CSR construction ------------------------------------------
__global__ void k_deginit(int n) {
    int i = blockIdx.x * blockDim.x + threadIdx.x;
    if (i < n) g_deg[i] = 1;  // self-loop
}
__global__ void k_hist(const void* ei, int E) {
    int is64 = g_is64;
    for (int i = blockIdx.x * blockDim.x + threadIdx.x; i < E; i += gridDim.x * blockDim.x) {
        int d = edge_at(ei, (long long)E + i, is64);
        atomicAdd(&g_deg[d], 1);
    }
}
__global__ void k_scan1(int n) {
    __shared__ int ssum[256];
    int b = blockIdx.x, t = threadIdx.x;
    int base = b * 1024 + t * 4;
    int v[4];
    int tsum = 0;
#pragma unroll
    for (int j = 0; j < 4; j++) {
        int idx = base + j;
        v[j] = (idx < n) ? g_deg[idx] : 0;
        tsum += v[j];
    }
    ssum[t] = tsum;
    __syncthreads();
    for (int off = 1; off < 256; off <<= 1) {
        int x = (t >= off) ? ssum[t - off] : 0;
        __syncthreads();
        ssum[t] += x;
        __syncthreads();
    }
    int run = ssum[t] - tsum;
#pragma unroll
    for (int j = 0; j < 4; j++) {
        run += v[j];
        if (base + j < n) g_rowptr[base + j + 1] = run;
    }
    if (t == 255) g_part[b] = ssum[255];
}
__global__ void k_scan2(int nb) {
    if (threadIdx.x == 0 && blockIdx.x == 0) {
        int run = 0;
        for (int b = 0; b < nb; b++) {
            int t = g_part[b];
            g_part[b] = run;
            run += t;
        }
        g_rowptr[0] = 0;
        g_cursor[0] = 0;
    }
}
__global__ void k_scan3(int n) {
    int b = blockIdx.x, t = threadIdx.x;
    int off = g_part[b];
    int base = b * 1024 + t * 4;
#pragma unroll
    for (int j = 0; j < 4; j++) {
        int idx = base + j;
        if (idx < n) {
            int v = g_rowptr[idx + 1] + off;
            g_rowptr[idx + 1] = v;
            g_cursor[idx + 1] = v;
        }
    }
}
__global__ void k_fill(const void* ei, int E, int n) {
    int is64 = g_is64;
    int total = E + n;
    for (int i = blockIdx.x * blockDim.x + threadIdx.x; i < total; i += gridDim.x * blockDim.x) {
        int s, d;
        if (i < E) {
            s = edge_at(ei, i, is64);
            d = edge_at(ei, (long long)E + i, is64);
        } else {
            s = d = i - E;
        }
        int p = atomicAdd(&g_cursor[d], 1);
        g_csrsrc[p] = s;
    }
}

// ---------------- layer1 fused ONLINE softmax + gather + bias + elu ---------
// warp per node; each lane owns one uint4 (8 bf16 feats) and 2 heads.
__global__ void k_gather1(const float* __restrict__ b1, int n) {
    int w = (blockIdx.x * blockDim.x + threadIdx.x) >> 5;
    int lane = threadIdx.x & 31;
    if (w >= n) return;
    int beg = g_rowptr[w], end = g_rowptr[w + 1];
    int deg = end - beg;
    int hlo = lane >> 3, hhi = hlo + 4;
    float ad_lo = g_ad1[w * HH + hlo], ad_hi = g_ad1[w * HH + hhi];
    float m_lo = -1e30f, m_hi = -1e30f, s_lo = 0.f, s_hi = 0.f;
    float4 alo = make_float4(0.f, 0.f, 0.f, 0.f);
    float4 ahi = make_float4(0.f, 0.f, 0.f, 0.f);
    const uint4* h1bv = (const uint4*)g_h1bf;
    for (int base = 0; base < deg; base += 32) {
        int cnt = min(32, deg - base);
        int s_l = 0;
        if (lane < cnt) s_l = g_csrsrc[beg + base + lane];
#pragma unroll 4
        for (int j = 0; j < cnt; j++) {
            int s = __shfl_sync(0xffffffffu, s_l, j);
            float v_lo = lrelu(g_as1[s * HH + hlo] + ad_lo);
            float v_hi = lrelu(g_as1[s * HH + hhi] + ad_hi);
            if (v_lo > m_lo) {
                float f = __expf(m_lo - v_lo);
                s_lo *= f;
                alo.x *= f; alo.y *= f; alo.z *= f; alo.w *= f;
                m_lo = v_lo;
            }
            if (v_hi > m_hi) {
                float f = __expf(m_hi - v_hi);
                s_hi *= f;
                ahi.x *= f; ahi.y *= f; ahi.z *= f; ahi.w *= f;
                m_hi = v_hi;
            }
            float wlo = __expf(v_lo - m_lo);
            float whi = __expf(v_hi - m_hi);
            s_lo += wlo;
            s_hi += whi;
            uint4 v = h1bv[(long long)s * 32 + lane];
            float2 x0 = __bfloat1622float2(*(__nv_bfloat162*)&v.x);
            float2 x1 = __bfloat1622float2(*(__nv_bfloat162*)&v.y);
            float2 x2 = __bfloat1622float2(*(__nv_bfloat162*)&v.z);
            float2 x3 = __bfloat1622float2(*(__nv_bfloat162*)&v.w);
            alo.x += wlo * x0.x; alo.y += wlo * x0.y;
            alo.z += wlo * x1.x; alo.w += wlo * x1.y;
            ahi.x += whi * x2.x; ahi.y += whi * x2.y;
            ahi.z += whi * x3.x; ahi.w += whi * x3.y;
        }
    }
    float iv_lo = 1.f / (s_lo + 1e-16f);
    float iv_hi = 1.f / (s_hi + 1e-16f);
    float4 blo = ((const float4*)b1)[lane];
    float4 bhi = ((const float4*)b1)[lane + 32];
    float4 r0, r1;
    r0.x = eluf(alo.x * iv_lo + blo.x); r0.y = eluf(alo.y * iv_lo + blo.y);
    r0.z = eluf(alo.z * iv_lo + blo.z); r0.w = eluf(alo.w * iv_lo + blo.w);
    r1.x = eluf(ahi.x * iv_hi + bhi.x); r1.y = eluf(ahi.y * iv_hi + bhi.y);
    r1.z = eluf(ahi.z * iv_hi + bhi.z); r1.w = eluf(ahi.w * iv_hi + bhi.w);
    ((float4*)g_h2)[(long long)w * 64 + lane] = r0;
    ((float4*)g_h2)[(long long)w * 64 + lane + 32] = r1;
}

// ---------------- GEMM2 fused: g = h2@W2 + layer2 att scores (f32x2) --------
__global__ void k_gemm2f(const float* __restrict__ W2,
                         const float* __restrict__ a2s_, const float* __restrict__ a2d_, int n) {
    const int BM = 256, BK = 16;
    __shared__ float h2s[BM][BK + 1];
    __shared__ float W2s[BK * NC];
    __shared__ float s2s[BM];
    __shared__ float s2d[BM];
    int t = threadIdx.x;
    int rg = t >> 2;   // 0..63  -> 4 rows each
    int q = t & 3;     // 0..3   -> 10 cols each
    int bm0 = blockIdx.x * BM;
    s2s[t] = 0.f;
    s2d[t] = 0.f;
    unsigned long long acc2[4][5];
#pragma unroll
    for (int i = 0; i < 4; i++)
#pragma unroll
        for (int p = 0; p < 5; p++) acc2[i][p] = 0ull;

    for (int kc = 0; kc < F1; kc += BK) {
#pragma unroll
        for (int j = 0; j < 4; j++) {
            int li = t + 256 * j;
            int row = li >> 2;
            int c4 = li & 3;
            float4 v = make_float4(0.f, 0.f, 0.f, 0.f);
            if (bm0 + row < n)
                v = *(const float4*)&g_h2[(long long)(bm0 + row) * F1 + kc + c4 * 4];
            h2s[row][c4 * 4 + 0] = v.x;
            h2s[row][c4 * 4 + 1] = v.y;
            h2s[row][c4 * 4 + 2] = v.z;
            h2s[row][c4 * 4 + 3] = v.w;
        }
        if (t < 160)
            *(float4*)&W2s[t * 4] = *(const float4*)&W2[kc * NC + t * 4];
        __syncthreads();
#pragma unroll
        for (int k = 0; k < BK; k++) {
            unsigned long long b2[5];
#pragma unroll
            for (int p = 0; p < 5; p++)
                b2[p] = *(const unsigned long long*)&W2s[k * NC + q * 10 + 2 * p];
            unsigned long long a0 = pkdup(h2s[rg * 4 + 0][k]);
            unsigned long long a1 = pkdup(h2s[rg * 4 + 1][k]);
            unsigned long long a2 = pkdup(h2s[rg * 4 + 2][k]);
            unsigned long long a3 = pkdup(h2s[rg * 4 + 3][k]);
#pragma unroll
            for (int p = 0; p < 5; p++) {
                ffma2(acc2[0][p], a0, b2[p]);
                ffma2(acc2[1][p], a1, b2[p]);
                ffma2(acc2[2][p], a2, b2[p]);
                ffma2(acc2[3][p], a3, b2[p]);
            }
        }
        __syncthreads();
    }
    float acc[4][10];
#pragma unroll
    for (int i = 0; i < 4; i++)
#pragma unroll
        for (int p = 0; p < 5; p++) {
            float2 v = unpk(acc2[i][p]);
            acc[i][2 * p] = v.x;
            acc[i][2 * p + 1] = v.y;
        }
    float cs[10], cd[10];
#pragma unroll
    for (int j = 0; j < 10; j++) {
        cs[j] = a2s_[q * 10 + j];
        cd[j] = a2d_[q * 10 + j];
    }
#pragma unroll
    for (int i = 0; i < 4; i++) {
        int r = rg * 4 + i;
        int row = bm0 + r;
        float ps = 0.f, pd = 0.f;
#pragma unroll
        for (int j = 0; j < 10; j++) {
            ps += acc[i][j] * cs[j];
            pd += acc[i][j] * cd[j];
        }
        atomicAdd(&s2s[r], ps);
        atomicAdd(&s2d[r], pd);
        if (row < n) {
#pragma unroll
            for (int j = 0; j < 10; j++) g_g[(long long)row * NC + q * 10 + j] = acc[i][j];
        }
    }
    __syncthreads();
    if (bm0 + t < n) {
        g_a2s[bm0 + t] = s2s[t];
        g_a2d[bm0 + t] = s2d[t];
    }
}

// ---------------- layer2 fused ONLINE softmax gather + bias + log_softmax ---
__global__ void k_gather2(const float* __restrict__ b2, float* __restrict__ out, int n) {
    int w = (blockIdx.x * blockDim.x + threadIdx.x) >> 5;
    int lane = threadIdx.x & 31;
    if (w >= n) return;
    int beg = g_rowptr[w], end = g_rowptr[w + 1];
    int deg = end - beg;
    float ad = g_a2d[w];
    float m = -1e30f, sum = 0.f;
    float acc_lo = 0.f, acc_hi = 0.f;
    for (int base = 0; base < deg; base += 32) {
        int cnt = min(32, deg - base);
        int s_l = 0;
        if (lane < cnt) s_l = g_csrsrc[beg + base + lane];
#pragma unroll 4
        for (int j = 0; j < cnt; j++) {
            int s = __shfl_sync(0xffffffffu, s_l, j);
            float v = lrelu(g_a2s[s] + ad);
            if (v > m) {
                float f = __expf(m - v);
                sum *= f;
                acc_lo *= f;
                acc_hi *= f;
                m = v;
            }
            float wg = __expf(v - m);
            sum += wg;
            acc_lo += wg * g_g[(long long)s * NC + lane];
            if (lane < 8) acc_hi += wg * g_g[(long long)s * NC + 32 + lane];
        }
    }
    float iv = 1.f / (sum + 1e-16f);
    float v_lo = acc_lo * iv + b2[lane];
    float v_hi = (lane < 8) ? (acc_hi * iv + b2[32 + lane]) : -1e30f;
    float lm = fmaxf(v_lo, v_hi);
#pragma unroll
    for (int off = 16; off > 0; off >>= 1)
        lm = fmaxf(lm, __shfl_xor_sync(0xffffffffu, lm, off));
    float se = __expf(v_lo - lm) + ((lane < 8) ? __expf(v_hi - lm) : 0.f);
#pragma unroll
    for (int off = 16; off > 0; off >>= 1)
        se += __shfl_xor_sync(0xffffffffu, se, off);
    float ls = lm + logf(se);
    out[(long long)w * NC + lane] = v_lo - ls;
    if (lane < 8) out[(long long)w * NC + 32 + lane] = v_hi - ls;
}

// ---------------- launch -----------------------------------------------------
extern "C" void kernel_launch(void* const* d_in, const int* in_sizes, int n_in,
                              void* d_out, int out_size) {
    const float* x    = (const float*)d_in[0];
    const void*  ei   = d_in[1];
    const float* W1   = (const float*)d_in[2];
    const float* a1s  = (const float*)d_in[3];
    const float* a1d  = (const float*)d_in[4];
    const float* b1   = (const float*)d_in[5];
    const float* W2   = (const float*)d_in[6];
    const float* a2s  = (const float*)d_in[7];
    const float* a2d  = (const float*)d_in[8];
    const float* b2   = (const float*)d_in[9];
    float* out = (float*)d_out;

    int n = in_sizes[0] / FIN;
    int E = in_sizes[1] / 2;
    int nb = (n + 1023) / 1024;
    int wpb = (n + 7) / 8;  // warp-per-node grids (8 warps / 256-thread block)

    static cudaStream_t s2 = nullptr;
    static cudaEvent_t ev_fork = nullptr, ev_join = nullptr;
    if (!s2) {
        cudaStreamCreateWithFlags(&s2, cudaStreamNonBlocking);
        cudaEventCreateWithFlags(&ev_fork, cudaEventDisableTiming);
        cudaEventCreateWithFlags(&ev_join, cudaEventDisableTiming);
    }

    // fork: CSR build on s2, GEMM1 on main stream
    cudaEventRecord(ev_fork, 0);
    cudaStreamWaitEvent(s2, ev_fork, 0);

    k_detect<<<1, 256, 0, s2>>>(ei, n);
    k_deginit<<<(n + 255) / 256, 256, 0, s2>>>(n);
    k_hist<<<512, 256, 0, s2>>>(ei, E);
    k_scan1<<<nb, 256, 0, s2>>>(n);
    k_scan2<<<1, 32, 0, s2>>>(nb);
    k_scan3<<<nb, 256, 0, s2>>>(n);
    k_fill<<<832, 256, 0, s2>>>(ei, E, n);

    k_gemm1f<<<(n + 63) / 64, 256>>>(x, W1, a1s, a1d, n);

    // join
    cudaEventRecord(ev_join, s2);
    cudaStreamWaitEvent(0, ev_join, 0);

    k_gather1<<<wpb, 256>>>(b1, n);
    k_gemm2f<<<(n + 255) / 256, 256>>>(W2, a2s, a2d, n);
    k_gather2<<<wpb, 256>>>(b2, out, n);
}

// round 10
// speedup vs baseline: 1.0777x; 1.0777x over previous
#include <cuda_runtime.h>
#include <cuda_bf16.h>
#include <math.h>

#define NN 50000
#define FIN 128
#define F1 256
#define HH 8
#define CH 32
#define NC 40
#define EMAX 1000000

// ---------------- scratch (device globals; no allocation allowed) -----------
__device__ __nv_bfloat16 g_h1bf[NN * F1];  // layer1 features, bf16, lane-permuted layout
__device__ float g_h2[NN * F1];            // elu(aggregated + b1)
__device__ float g_as1[NN * HH];
__device__ float g_ad1[NN * HH];
__device__ float g_fm1[NN * HH];
__device__ float g_inv1[NN * HH];
__device__ float g_g[NN * NC];             // layer2 per-node features
__device__ float g_a2s[NN];
__device__ float g_a2d[NN];
__device__ float g_fm2[NN];
__device__ float g_inv2[NN];
__device__ int   g_deg[NN];
__device__ int   g_rowptr[NN + 1];
__device__ int   g_cursor[NN + 1];
__device__ int   g_csrsrc[EMAX];
__device__ int   g_part[64];
__device__ int   g_is64;

// ---------------- helpers ---------------------------------------------------
__device__ __forceinline__ int edge_at(const void* p, long long i, int is64) {
    if (is64) return (int)((const long long*)p)[i];
    return ((const int*)p)[i];
}
__device__ __forceinline__ float lrelu(float v) { return v > 0.f ? v : 0.2f * v; }
__device__ __forceinline__ float eluf(float v) { return v > 0.f ? v : (__expf(v) - 1.f); }

__device__ __forceinline__ unsigned long long pkdup(float a) {
    unsigned long long r;
    asm("mov.b64 %0, {%1, %1};" : "=l"(r) : "f"(a));
    return r;
}
__device__ __forceinline__ unsigned long long pk2(float lo, float hi) {
    unsigned long long r;
    asm("mov.b64 %0, {%1, %2};" : "=l"(r) : "f"(lo), "f"(hi));
    return r;
}
__device__ __forceinline__ float2 unpk(unsigned long long v) {
    float2 r;
    asm("mov.b64 {%0, %1}, %2;" : "=f"(r.x), "=f"(r.y) : "l"(v));
    return r;
}
__device__ __forceinline__ void ffma2(unsigned long long& acc, unsigned long long a, unsigned long long b) {
    asm("fma.rn.f32x2 %0, %1, %2, %0;" : "+l"(acc) : "l"(a), "l"(b));
}

// ---------------- dtype detection ------------------------------------------
__global__ void k_detect(const void* ei, int n) {
    int bad = 0;
    for (int i = threadIdx.x; i < 1024; i += blockDim.x) {
        long long v = ((const long long*)ei)[i];
        if (v < 0 || v >= n) bad = 1;
    }
    int anybad = __syncthreads_or(bad);
    if (threadIdx.x == 0) g_is64 = anybad ? 0 : 1;
}

// ---------------- GEMM1 fused: h1 = x@W1, att scores, bf16 permuted output --
// BM=64, BN=256 (full width), BK=16, 256 threads, 8x8 per thread, f32x2 FMA.
__global__ void k_gemm1f(const float* __restrict__ x, const float* __restrict__ W1,
                         const float* __restrict__ a1s_, const float* __restrict__ a1d_, int n) {
    const int BM = 64, BK = 16;
    __shared__ float As[BK][BM];
    __shared__ float Bs[BK][F1];
    __shared__ float sas[BM][HH];
    __shared__ float sad[BM][HH];
    int t = threadIdx.x;
    int tx = t & 31;        // col group: cols tx*8..tx*8+7
    int ty = t >> 5;        // row group: rows ty*8..ty*8+7
    int bm0 = blockIdx.x * BM;

    for (int i = t; i < BM * HH; i += 256) {
        ((float*)sas)[i] = 0.f;
        ((float*)sad)[i] = 0.f;
    }

    unsigned long long acc2[8][4];
#pragma unroll
    for (int i = 0; i < 8; i++)
#pragma unroll
        for (int p = 0; p < 4; p++) acc2[i][p] = 0ull;

    int arow = t >> 2, akc = (t & 3) * 4;

    for (int kk = 0; kk < FIN; kk += BK) {
        float4 av = make_float4(0.f, 0.f, 0.f, 0.f);
        if (bm0 + arow < n)
            av = *(const float4*)&x[(long long)(bm0 + arow) * FIN + kk + akc];
        As[akc + 0][arow] = av.x;
        As[akc + 1][arow] = av.y;
        As[akc + 2][arow] = av.z;
        As[akc + 3][arow] = av.w;
#pragma unroll
        for (int j = 0; j < 4; j++) {
            int f4 = t + 256 * j;
            int brow = f4 >> 6, bcol = (f4 & 63) * 4;
            *(float4*)&Bs[brow][bcol] = *(const float4*)&W1[(long long)(kk + brow) * F1 + bcol];
        }
        __syncthreads();
#pragma unroll
        for (int k = 0; k < BK; k++) {
            float a[8];
            *(float4*)&a[0] = *(float4*)&As[k][ty * 8];
            *(float4*)&a[4] = *(float4*)&As[k][ty * 8 + 4];
            float4 bv0 = *(float4*)&Bs[k][tx * 8];
            float4 bv1 = *(float4*)&Bs[k][tx * 8 + 4];
            unsigned long long b2[4];
            b2[0] = pk2(bv0.x, bv0.y);
            b2[1] = pk2(bv0.z, bv0.w);
            b2[2] = pk2(bv1.x, bv1.y);
            b2[3] = pk2(bv1.z, bv1.w);
#pragma unroll
            for (int i = 0; i < 8; i++) {
                unsigned long long ad = pkdup(a[i]);
#pragma unroll
                for (int p = 0; p < 4; p++) ffma2(acc2[i][p], ad, b2[p]);
            }
        }
        __syncthreads();
    }

    // unpack accumulators
    float acc[8][8];
#pragma unroll
    for (int i = 0; i < 8; i++)
#pragma unroll
        for (int p = 0; p < 4; p++) {
            float2 v = unpk(acc2[i][p]);
            acc[i][2 * p] = v.x;
            acc[i][2 * p + 1] = v.y;
        }

    float cs[8], cd[8];
#pragma unroll
    for (int j = 0; j < 8; j++) {
        cs[j] = a1s_[tx * 8 + j];
        cd[j] = a1d_[tx * 8 + j];
    }
    int hh = tx >> 2;

    int base_e = (tx < 16) ? tx * 16 : (tx - 16) * 16 + 4;
#pragma unroll
    for (int i = 0; i < 8; i++) {
        int r = ty * 8 + i;
        int row = bm0 + r;
        float ps = 0.f, pd = 0.f;
#pragma unroll
        for (int j = 0; j < 8; j++) {
            ps += acc[i][j] * cs[j];
            pd += acc[i][j] * cd[j];
        }
        atomicAdd(&sas[r][hh], ps);
        atomicAdd(&sad[r][hh], pd);
        if (row < n) {
            __nv_bfloat162 p01 = __floats2bfloat162_rn(acc[i][0], acc[i][1]);
            __nv_bfloat162 p23 = __floats2bfloat162_rn(acc[i][2], acc[i][3]);
            __nv_bfloat162 p45 = __floats2bfloat162_rn(acc[i][4], acc[i][5]);
            __nv_bfloat162 p67 = __floats2bfloat162_rn(acc[i][6], acc[i][7]);
            __nv_bfloat162* dst = (__nv_bfloat162*)&g_h1bf[(long long)row * F1 + base_e];
            dst[0] = p01;
            dst[1] = p23;
            __nv_bfloat162* dst2 = (__nv_bfloat162*)&g_h1bf[(long long)row * F1 + base_e + 8];
            dst2[0] = p45;
            dst2[1] = p67;
        }
    }
    __syncthreads();
    for (int idx = t; idx < BM * HH; idx += 256) {
        int r = idx >> 3, h = idx & 7;
        if (bm0 + r < n) {
            g_as1[(bm0 + r) * HH + h] = sas[r][h];
            g_ad1[(bm0 + r) * HH + h] = sad[r][h];
        }
    }
}

// ---------------- CSR construction ------------------------------------------
__global__ void k_deginit(int n) {
    int i = blockIdx.x * blockDim.x + threadIdx.x;
    if (i < n) g_deg[i] = 1;  // self-loop
}
__global__ void k_hist(const void* ei, int E) {
    int is64 = g_is64;
    for (int i = blockIdx.x * blockDim.x + threadIdx.x; i < E; i += gridDim.x * blockDim.x) {
        int d = edge_at(ei, (long long)E + i, is64);
        atomicAdd(&g_deg[d], 1);
    }
}
__global__ void k_scan1(int n) {
    __shared__ int ssum[256];
    int b = blockIdx.x, t = threadIdx.x;
    int base = b * 1024 + t * 4;
    int v[4];
    int tsum = 0;
#pragma unroll
    for (int j = 0; j < 4; j++) {
        int idx = base + j;
        v[j] = (idx < n) ? g_deg[idx] : 0;
        tsum += v[j];
    }
    ssum[t] = tsum;
    __syncthreads();
    for (int off = 1; off < 256; off <<= 1) {
        int x = (t >= off) ? ssum[t - off] : 0;
        __syncthreads();
        ssum[t] += x;
        __syncthreads();
    }
    int run = ssum[t] - tsum;
#pragma unroll
    for (int j = 0; j < 4; j++) {
        run += v[j];
        if (base + j < n) g_rowptr[base + j + 1] = run;
    }
    if (t == 255) g_part[b] = ssum[255];
}
__global__ void k_scan2(int nb) {
    if (threadIdx.x == 0 && blockIdx.x == 0) {
        int run = 0;
        for (int b = 0; b < nb; b++) {
            int t = g_part[b];
            g_part[b] = run;
            run += t;
        }
        g_rowptr[0] = 0;
        g_cursor[0] = 0;
    }
}
__global__ void k_scan3(int n) {
    int b = blockIdx.x, t = threadIdx.x;
    int off = g_part[b];
    int base = b * 1024 + t * 4;
#pragma unroll
    for (int j = 0; j < 4; j++) {
        int idx = base + j;
        if (idx < n) {
            int v = g_rowptr[idx + 1] + off;
            g_rowptr[idx + 1] = v;
            g_cursor[idx + 1] = v;
        }
    }
}
__global__ void k_fill(const void* ei, int E, int n) {
    int is64 = g_is64;
    int total = E + n;
    for (int i = blockIdx.x * blockDim.x + threadIdx.x; i < total; i += gridDim.x * blockDim.x) {
        int s, d;
        if (i < E) {
            s = edge_at(ei, i, is64);
            d = edge_at(ei, (long long)E + i, is64);
        } else {
            s = d = i - E;
        }
        int p = atomicAdd(&g_cursor[d], 1);
        g_csrsrc[p] = s;
    }
}

// ---------------- layer1 softmax normalizers (warp per node) ----------------
__global__ void k_maxsum1(int n) {
    int w = (blockIdx.x * blockDim.x + threadIdx.x) >> 5;
    int lane = threadIdx.x & 31;
    if (w >= n) return;
    int beg = g_rowptr[w], end = g_rowptr[w + 1];
    int h = lane & 7, slot = lane >> 3;   // 4 edge-slots x 8 heads
    float ad = g_ad1[w * HH + h];
    float mx = -1e30f;
    for (int e = beg + slot; e < end; e += 4) {
        int s = g_csrsrc[e];
        mx = fmaxf(mx, lrelu(g_as1[s * HH + h] + ad));
    }
    mx = fmaxf(mx, __shfl_xor_sync(0xffffffffu, mx, 8));
    mx = fmaxf(mx, __shfl_xor_sync(0xffffffffu, mx, 16));
    float sm = 0.f;
    for (int e = beg + slot; e < end; e += 4) {
        int s = g_csrsrc[e];
        sm += __expf(lrelu(g_as1[s * HH + h] + ad) - mx);
    }
    sm += __shfl_xor_sync(0xffffffffu, sm, 8);
    sm += __shfl_xor_sync(0xffffffffu, sm, 16);
    if (lane < HH) {
        g_fm1[w * HH + lane] = mx;
        g_inv1[w * HH + lane] = 1.f / (sm + 1e-16f);
    }
}

// ---------------- layer1 fused weight+gather+bias+elu (warp per node) -------
// Each lane reads ONE uint4 (8 bf16) per edge: feats {4l..4l+3, 128+4l..128+4l+3}.
__global__ void k_gather1(const float* __restrict__ b1, int n) {
    int w = (blockIdx.x * blockDim.x + threadIdx.x) >> 5;
    int lane = threadIdx.x & 31;
    if (w >= n) return;
    int beg = g_rowptr[w], end = g_rowptr[w + 1];
    int deg = end - beg;
    int hlo = lane >> 3, hhi = hlo + 4;
    float ad_lo = g_ad1[w * HH + hlo], ad_hi = g_ad1[w * HH + hhi];
    float fm_lo = g_fm1[w * HH + hlo], fm_hi = g_fm1[w * HH + hhi];
    float iv_lo = g_inv1[w * HH + hlo], iv_hi = g_inv1[w * HH + hhi];
    float4 alo = make_float4(0.f, 0.f, 0.f, 0.f);
    float4 ahi = make_float4(0.f, 0.f, 0.f, 0.f);
    const uint4* h1bv = (const uint4*)g_h1bf;
    for (int base = 0; base < deg; base += 32) {
        int cnt = min(32, deg - base);
        int s_l = 0;
        if (lane < cnt) s_l = g_csrsrc[beg + base + lane];
#pragma unroll 4
        for (int j = 0; j < cnt; j++) {
            int s = __shfl_sync(0xffffffffu, s_l, j);
            float wlo = __expf(lrelu(g_as1[s * HH + hlo] + ad_lo) - fm_lo) * iv_lo;
            float whi = __expf(lrelu(g_as1[s * HH + hhi] + ad_hi) - fm_hi) * iv_hi;
            uint4 v = h1bv[(long long)s * 32 + lane];
            float2 x0 = __bfloat1622float2(*(__nv_bfloat162*)&v.x);
            float2 x1 = __bfloat1622float2(*(__nv_bfloat162*)&v.y);
            float2 x2 = __bfloat1622float2(*(__nv_bfloat162*)&v.z);
            float2 x3 = __bfloat1622float2(*(__nv_bfloat162*)&v.w);
            alo.x += wlo * x0.x; alo.y += wlo * x0.y;
            alo.z += wlo * x1.x; alo.w += wlo * x1.y;
            ahi.x += whi * x2.x; ahi.y += whi * x2.y;
            ahi.z += whi * x3.x; ahi.w += whi * x3.y;
        }
    }
    float4 blo = ((const float4*)b1)[lane];
    float4 bhi = ((const float4*)b1)[lane + 32];
    float4 r0, r1;
    r0.x = eluf(alo.x + blo.x); r0.y = eluf(alo.y + blo.y);
    r0.z = eluf(alo.z + blo.z); r0.w = eluf(alo.w + blo.w);
    r1.x = eluf(ahi.x + bhi.x); r1.y = eluf(ahi.y + bhi.y);
    r1.z = eluf(ahi.z + bhi.z); r1.w = eluf(ahi.w + bhi.w);
    ((float4*)g_h2)[(long long)w * 64 + lane] = r0;
    ((float4*)g_h2)[(long long)w * 64 + lane + 32] = r1;
}

// ---------------- GEMM2 fused: g = h2@W2 + layer2 att scores (f32x2) --------
__global__ void k_gemm2f(const float* __restrict__ W2,
                         const float* __restrict__ a2s_, const float* __restrict__ a2d_, int n) {
    const int BM = 256, BK = 16;
    __shared__ float h2s[BM][BK + 1];
    __shared__ float W2s[BK * NC];
    __shared__ float s2s[BM];
    __shared__ float s2d[BM];
    int t = threadIdx.x;
    int rg = t >> 2;   // 0..63  -> 4 rows each
    int q = t & 3;     // 0..3   -> 10 cols each
    int bm0 = blockIdx.x * BM;
    s2s[t] = 0.f;
    s2d[t] = 0.f;
    unsigned long long acc2[4][5];
#pragma unroll
    for (int i = 0; i < 4; i++)
#pragma unroll
        for (int p = 0; p < 5; p++) acc2[i][p] = 0ull;

    for (int kc = 0; kc < F1; kc += BK) {
#pragma unroll
        for (int j = 0; j < 4; j++) {
            int li = t + 256 * j;
            int row = li >> 2;
            int c4 = li & 3;
            float4 v = make_float4(0.f, 0.f, 0.f, 0.f);
            if (bm0 + row < n)
                v = *(const float4*)&g_h2[(long long)(bm0 + row) * F1 + kc + c4 * 4];
            h2s[row][c4 * 4 + 0] = v.x;
            h2s[row][c4 * 4 + 1] = v.y;
            h2s[row][c4 * 4 + 2] = v.z;
            h2s[row][c4 * 4 + 3] = v.w;
        }
        if (t < 160)
            *(float4*)&W2s[t * 4] = *(const float4*)&W2[kc * NC + t * 4];
        __syncthreads();
#pragma unroll
        for (int k = 0; k < BK; k++) {
            unsigned long long b2[5];
#pragma unroll
            for (int p = 0; p < 5; p++)
                b2[p] = *(const unsigned long long*)&W2s[k * NC + q * 10 + 2 * p];
            unsigned long long a0 = pkdup(h2s[rg * 4 + 0][k]);
            unsigned long long a1 = pkdup(h2s[rg * 4 + 1][k]);
            unsigned long long a2 = pkdup(h2s[rg * 4 + 2][k]);
            unsigned long long a3 = pkdup(h2s[rg * 4 + 3][k]);
#pragma unroll
            for (int p = 0; p < 5; p++) {
                ffma2(acc2[0][p], a0, b2[p]);
                ffma2(acc2[1][p], a1, b2[p]);
                ffma2(acc2[2][p], a2, b2[p]);
                ffma2(acc2[3][p], a3, b2[p]);
            }
        }
        __syncthreads();
    }
    float acc[4][10];
#pragma unroll
    for (int i = 0; i < 4; i++)
#pragma unroll
        for (int p = 0; p < 5; p++) {
            float2 v = unpk(acc2[i][p]);
            acc[i][2 * p] = v.x;
            acc[i][2 * p + 1] = v.y;
        }
    float cs[10], cd[10];
#pragma unroll
    for (int j = 0; j < 10; j++) {
        cs[j] = a2s_[q * 10 + j];
        cd[j] = a2d_[q * 10 + j];
    }
#pragma unroll
    for (int i = 0; i < 4; i++) {
        int r = rg * 4 + i;
        int row = bm0 + r;
        float ps = 0.f, pd = 0.f;
#pragma unroll
        for (int j = 0; j < 10; j++) {
            ps += acc[i][j] * cs[j];
            pd += acc[i][j] * cd[j];
        }
        atomicAdd(&s2s[r], ps);
        atomicAdd(&s2d[r], pd);
        if (row < n) {
#pragma unroll
            for (int j = 0; j < 10; j++) g_g[(long long)row * NC + q * 10 + j] = acc[i][j];
        }
    }
    __syncthreads();
    if (bm0 + t < n) {
        g_a2s[bm0 + t] = s2s[t];
        g_a2d[bm0 + t] = s2d[t];
    }
}

// ---------------- layer2 softmax normalizers (warp per node) ----------------
__global__ void k_maxsum2(int n) {
    int w = (blockIdx.x * blockDim.x + threadIdx.x) >> 5;
    int lane = threadIdx.x & 31;
    if (w >= n) return;
    int beg = g_rowptr[w], end = g_rowptr[w + 1];
    float ad = g_a2d[w];
    float mx = -1e30f;
    for (int e = beg + lane; e < end; e += 32)
        mx = fmaxf(mx, lrelu(g_a2s[g_csrsrc[e]] + ad));
#pragma unroll
    for (int off = 16; off > 0; off >>= 1)
        mx = fmaxf(mx, __shfl_xor_sync(0xffffffffu, mx, off));
    float sm = 0.f;
    for (int e = beg + lane; e < end; e += 32)
        sm += __expf(lrelu(g_a2s[g_csrsrc[e]] + ad) - mx);
#pragma unroll
    for (int off = 16; off > 0; off >>= 1)
        sm += __shfl_xor_sync(0xffffffffu, sm, off);
    if (lane == 0) {
        g_fm2[w] = mx;
        g_inv2[w] = 1.f / (sm + 1e-16f);
    }
}

// ---------------- layer2 fused gather + bias + log_softmax (warp per node) --
__global__ void k_gather2(const float* __restrict__ b2, float* __restrict__ out, int n) {
    int w = (blockIdx.x * blockDim.x + threadIdx.x) >> 5;
    int lane = threadIdx.x & 31;
    if (w >= n) return;
    int beg = g_rowptr[w], end = g_rowptr[w + 1];
    int deg = end - beg;
    float ad = g_a2d[w], m = g_fm2[w], iv = g_inv2[w];
    float acc_lo = 0.f, acc_hi = 0.f;
    for (int base = 0; base < deg; base += 32) {
        int cnt = min(32, deg - base);
        int s_l = 0;
        if (lane < cnt) s_l = g_csrsrc[beg + base + lane];
#pragma unroll 4
        for (int j = 0; j < cnt; j++) {
            int s = __shfl_sync(0xffffffffu, s_l, j);
            float wg = __expf(lrelu(g_a2s[s] + ad) - m) * iv;
            acc_lo += wg * g_g[(long long)s * NC + lane];
            if (lane < 8) acc_hi += wg * g_g[(long long)s * NC + 32 + lane];
        }
    }
    float v_lo = acc_lo + b2[lane];
    float v_hi = (lane < 8) ? (acc_hi + b2[32 + lane]) : -1e30f;
    float lm = fmaxf(v_lo, v_hi);
#pragma unroll
    for (int off = 16; off > 0; off >>= 1)
        lm = fmaxf(lm, __shfl_xor_sync(0xffffffffu, lm, off));
    float se = __expf(v_lo - lm) + ((lane < 8) ? __expf(v_hi - lm) : 0.f);
#pragma unroll
    for (int off = 16; off > 0; off >>= 1)
        se += __shfl_xor_sync(0xffffffffu, se, off);
    float ls = lm + logf(se);
    out[(long long)w * NC + lane] = v_lo - ls;
    if (lane < 8) out[(long long)w * NC + 32 + lane] = v_hi - ls;
}

// ---------------- launch -----------------------------------------------------
extern "C" void kernel_launch(void* const* d_in, const int* in_sizes, int n_in,
                              void* d_out, int out_size) {
    const float* x    = (const float*)d_in[0];
    const void*  ei   = d_in[1];
    const float* W1   = (const float*)d_in[2];
    const float* a1s  = (const float*)d_in[3];
    const float* a1d  = (const float*)d_in[4];
    const float* b1   = (const float*)d_in[5];
    const float* W2   = (const float*)d_in[6];
    const float* a2s  = (const float*)d_in[7];
    const float* a2d  = (const float*)d_in[8];
    const float* b2   = (const float*)d_in[9];
    float* out = (float*)d_out;

    int n = in_sizes[0] / FIN;
    int E = in_sizes[1] / 2;
    int nb = (n + 1023) / 1024;
    int wpb = (n + 7) / 8;  // warp-per-node grids (8 warps / 256-thread block)

    static cudaStream_t s2 = nullptr;
    static cudaEvent_t ev_fork = nullptr, ev_join = nullptr;
    if (!s2) {
        cudaStreamCreateWithFlags(&s2, cudaStreamNonBlocking);
        cudaEventCreateWithFlags(&ev_fork, cudaEventDisableTiming);
        cudaEventCreateWithFlags(&ev_join, cudaEventDisableTiming);
    }

    // fork: CSR build on s2, GEMM1 on main stream
    cudaEventRecord(ev_fork, 0);
    cudaStreamWaitEvent(s2, ev_fork, 0);

    k_detect<<<1, 256, 0, s2>>>(ei, n);
    k_deginit<<<(n + 255) / 256, 256, 0, s2>>>(n);
    k_hist<<<512, 256, 0, s2>>>(ei, E);
    k_scan1<<<nb, 256, 0, s2>>>(n);
    k_scan2<<<1, 32, 0, s2>>>(nb);
    k_scan3<<<nb, 256, 0, s2>>>(n);
    k_fill<<<832, 256, 0, s2>>>(ei, E, n);

    k_gemm1f<<<(n + 63) / 64, 256>>>(x, W1, a1s, a1d, n);

    // join
    cudaEventRecord(ev_join, s2);
    cudaStreamWaitEvent(0, ev_join, 0);

    k_maxsum1<<<wpb, 256>>>(n);
    k_gather1<<<wpb, 256>>>(b1, n);
    k_gemm2f<<<(n + 255) / 256, 256>>>(W2, a2s, a2d, n);
    k_maxsum2<<<wpb, 256>>>(n);
    k_gather2<<<wpb, 256>>>(b2, out, n);
}